// round 4
// baseline (speedup 1.0000x reference)
#include <cuda_runtime.h>
#include <cuda_fp16.h>
#include <cstdint>

#define N_NODES 100000
#define N_EDGES 3200000
#define FEAT 128
#define HID 128
#define NCLS 64
#define NCHUNK 98          // ceil(100000/1024)

// ---------------- scratch (device globals: no allocation allowed) ----------
__device__ int g_cnt_d[N_NODES];
__device__ int g_cnt_s[N_NODES];
__device__ int g_off_d[N_NODES + 1];
__device__ int g_off_s[N_NODES + 1];
__device__ int g_cur_d[N_NODES];
__device__ int g_cur_s[N_NODES];
__device__ int g_chk[2 * NCHUNK];
__device__ int g_adj_d[N_EDGES];   // src ids bucketed by dst
__device__ int g_adj_s[N_EDGES];   // dst ids bucketed by src
__device__ __half g_feat_h[(size_t)N_NODES * FEAT];  // fp16 copy of features
__device__ __half g_agg_h[(size_t)N_NODES * FEAT];   // fp16 mean-aggregated
__device__ __half g_h2h[(size_t)N_NODES * NCLS];     // fp16 post-W_out hidden

// ---------------- 1. zero counters + convert feat -> fp16 ------------------
__global__ void k_zero() {
    int i = blockIdx.x * blockDim.x + threadIdx.x;
    int stride = gridDim.x * blockDim.x;
    for (; i < N_NODES; i += stride) {
        g_cnt_d[i] = 0;
        g_cnt_s[i] = 0;
    }
}

__global__ void k_feat16(const float* __restrict__ feat) {
    int i = blockIdx.x * blockDim.x + threadIdx.x;   // one float2 -> half2
    const int total = N_NODES * FEAT / 2;
    if (i >= total) return;
    float2 v = ((const float2*)feat)[i];
    ((half2*)g_feat_h)[i] = __floats2half2_rn(v.x, v.y);
}

// ---------------- 2. count degrees (4 edges/thread for MLP) ----------------
__global__ void k_count(const int* __restrict__ ei) {
    int i = blockIdx.x * blockDim.x + threadIdx.x;
    if (i >= N_EDGES / 4) return;
    int4 s4 = ((const int4*)ei)[i];
    int4 d4 = ((const int4*)(ei + N_EDGES))[i];
    atomicAdd(&g_cnt_s[s4.x], 1);
    atomicAdd(&g_cnt_s[s4.y], 1);
    atomicAdd(&g_cnt_s[s4.z], 1);
    atomicAdd(&g_cnt_s[s4.w], 1);
    atomicAdd(&g_cnt_d[d4.x], 1);
    atomicAdd(&g_cnt_d[d4.y], 1);
    atomicAdd(&g_cnt_d[d4.z], 1);
    atomicAdd(&g_cnt_d[d4.w], 1);
}

// ---------------- 3. parallel exclusive scan (3 phases) --------------------
__global__ void k_scan1() {
    __shared__ int wsum[32];
    int bx = blockIdx.x;
    int sel = bx >= NCHUNK ? 1 : 0;
    int chunk = bx - sel * NCHUNK;
    const int* cnt = sel ? g_cnt_s : g_cnt_d;
    int* off = sel ? g_off_s : g_off_d;
    int tid = threadIdx.x, lane = tid & 31, wid = tid >> 5;
    int i = chunk * 1024 + tid;
    int v = (i < N_NODES) ? cnt[i] : 0;
    int x = v;
#pragma unroll
    for (int o = 1; o < 32; o <<= 1) {
        int y = __shfl_up_sync(0xffffffffu, x, o);
        if (lane >= o) x += y;
    }
    if (lane == 31) wsum[wid] = x;
    __syncthreads();
    if (wid == 0) {
        int xx = wsum[lane];
#pragma unroll
        for (int o = 1; o < 32; o <<= 1) {
            int y = __shfl_up_sync(0xffffffffu, xx, o);
            if (lane >= o) xx += y;
        }
        wsum[lane] = xx;
    }
    __syncthreads();
    int excl = x - v + (wid > 0 ? wsum[wid - 1] : 0);
    if (i < N_NODES) off[i] = excl;
    if (tid == 1023) g_chk[sel * NCHUNK + chunk] = wsum[31];
}

__global__ void k_scan2() {
    __shared__ int sh[256];
    int tid = threadIdx.x;
    int sel = tid >> 7, idx = tid & 127;
    int v = (idx < NCHUNK) ? g_chk[sel * NCHUNK + idx] : 0;
    sh[tid] = v;
    __syncthreads();
#pragma unroll
    for (int o = 1; o < 128; o <<= 1) {
        int y = (idx >= o) ? sh[tid - o] : 0;
        __syncthreads();
        sh[tid] += y;
        __syncthreads();
    }
    if (idx < NCHUNK) g_chk[sel * NCHUNK + idx] = sh[tid] - v;  // exclusive
    if (tid == 0) {
        g_off_d[N_NODES] = N_EDGES;
        g_off_s[N_NODES] = N_EDGES;
    }
}

__global__ void k_scan3() {
    int bx = blockIdx.x;
    int sel = bx >= NCHUNK ? 1 : 0;
    int chunk = bx - sel * NCHUNK;
    int i = chunk * 1024 + threadIdx.x;
    if (i >= N_NODES) return;
    int add = g_chk[sel * NCHUNK + chunk];
    if (sel) {
        int p = g_off_s[i] + add;
        g_off_s[i] = p;
        g_cur_s[i] = p;
    } else {
        int p = g_off_d[i] + add;
        g_off_d[i] = p;
        g_cur_d[i] = p;
    }
}

// ---------------- 4. fill CSR buckets (4 edges/thread) ---------------------
__global__ void k_fill(const int* __restrict__ ei) {
    int i = blockIdx.x * blockDim.x + threadIdx.x;
    if (i >= N_EDGES / 4) return;
    int4 s4 = ((const int4*)ei)[i];
    int4 d4 = ((const int4*)(ei + N_EDGES))[i];
    int p0 = atomicAdd(&g_cur_d[d4.x], 1);
    int p1 = atomicAdd(&g_cur_d[d4.y], 1);
    int p2 = atomicAdd(&g_cur_d[d4.z], 1);
    int p3 = atomicAdd(&g_cur_d[d4.w], 1);
    g_adj_d[p0] = s4.x;
    g_adj_d[p1] = s4.y;
    g_adj_d[p2] = s4.z;
    g_adj_d[p3] = s4.w;
    int q0 = atomicAdd(&g_cur_s[s4.x], 1);
    int q1 = atomicAdd(&g_cur_s[s4.y], 1);
    int q2 = atomicAdd(&g_cur_s[s4.z], 1);
    int q3 = atomicAdd(&g_cur_s[s4.w], 1);
    g_adj_s[q0] = d4.x;
    g_adj_s[q1] = d4.y;
    g_adj_s[q2] = d4.z;
    g_adj_s[q3] = d4.w;
}

// ---------------- 5. mean aggregation: fp16 gather, fp32 accumulate --------
// warp per dst node; lane covers feature cols 4*lane..4*lane+3 (2x half2)
__global__ void k_aggregate() {
    int w = (blockIdx.x * blockDim.x + threadIdx.x) >> 5;
    if (w >= N_NODES) return;
    int lane = threadIdx.x & 31;
    int beg = g_off_d[w], end = g_off_d[w + 1];
    const uint2* F = (const uint2*)g_feat_h;   // row = 32 uint2 (128 halves)
    float ax = 0.f, ay = 0.f, az = 0.f, aw = 0.f;
    int j = beg;
    for (; j + 4 <= end; j += 4) {
        int s0 = g_adj_d[j + 0];
        int s1 = g_adj_d[j + 1];
        int s2 = g_adj_d[j + 2];
        int s3 = g_adj_d[j + 3];
        uint2 v0 = F[(size_t)s0 * 32 + lane];
        uint2 v1 = F[(size_t)s1 * 32 + lane];
        uint2 v2 = F[(size_t)s2 * 32 + lane];
        uint2 v3 = F[(size_t)s3 * 32 + lane];
        float2 a0 = __half22float2(*(half2*)&v0.x), b0 = __half22float2(*(half2*)&v0.y);
        float2 a1 = __half22float2(*(half2*)&v1.x), b1 = __half22float2(*(half2*)&v1.y);
        float2 a2 = __half22float2(*(half2*)&v2.x), b2 = __half22float2(*(half2*)&v2.y);
        float2 a3 = __half22float2(*(half2*)&v3.x), b3 = __half22float2(*(half2*)&v3.y);
        ax += a0.x + a1.x + a2.x + a3.x;
        ay += a0.y + a1.y + a2.y + a3.y;
        az += b0.x + b1.x + b2.x + b3.x;
        aw += b0.y + b1.y + b2.y + b3.y;
    }
    for (; j < end; j++) {
        int s0 = g_adj_d[j];
        uint2 v0 = F[(size_t)s0 * 32 + lane];
        float2 a0 = __half22float2(*(half2*)&v0.x), b0 = __half22float2(*(half2*)&v0.y);
        ax += a0.x; ay += a0.y; az += b0.x; aw += b0.y;
    }
    float inv = (end > beg) ? 1.0f / (float)(end - beg) : 0.0f;
    uint2 r;
    *(half2*)&r.x = __floats2half2_rn(ax * inv, ay * inv);
    *(half2*)&r.y = __floats2half2_rn(az * inv, aw * inv);
    ((uint2*)g_agg_h)[(size_t)w * 32 + lane] = r;
}

// ---------------- 6. fused MLP on tensor cores (tf32 mma.sync) -------------
#define SA 132
#define SB 20

__device__ __forceinline__ uint32_t f2tf32(float v) {
    uint32_t u;
    asm("cvt.rna.tf32.f32 %0, %1;" : "=r"(u) : "f"(v));
    return u;
}

__device__ __forceinline__ void mma_tf32(float c[4], uint32_t a0, uint32_t a1,
                                         uint32_t a2, uint32_t a3,
                                         uint32_t b0, uint32_t b1) {
    asm volatile(
        "mma.sync.aligned.m16n8k8.row.col.f32.tf32.tf32.f32 "
        "{%0,%1,%2,%3}, {%4,%5,%6,%7}, {%8,%9}, {%0,%1,%2,%3};"
        : "+f"(c[0]), "+f"(c[1]), "+f"(c[2]), "+f"(c[3])
        : "r"(a0), "r"(a1), "r"(a2), "r"(a3), "r"(b0), "r"(b1));
}

__global__ __launch_bounds__(256) void k_mlp(
    const float* __restrict__ feat,
    const float* __restrict__ W_l, const float* __restrict__ W_r,
    const float* __restrict__ W_out,
    const float* __restrict__ mask1, const float* __restrict__ mask2) {
    __shared__ __align__(16) float As[64 * SA];
    __shared__ __align__(16) float Bs[128 * SB];

    int tid = threadIdx.x;
    int lane = tid & 31, w = tid >> 5;
    int rw = w & 3, cw = w >> 2;
    int g = lane >> 2, t = lane & 3;
    int n0 = blockIdx.x * 64;

    float acc[8][4];
#pragma unroll
    for (int j = 0; j < 8; j++)
#pragma unroll
        for (int q = 0; q < 4; q++) acc[j][q] = 0.f;

    // ---- stage 1: pass 0 = agg(fp16)@W_l, pass 1 = feat(fp32)@W_r ----
    for (int p = 0; p < 2; p++) {
        const float* W = p ? W_r : W_l;
        __syncthreads();
        for (int idx = tid; idx < 64 * 128; idx += 256) {
            int i = idx >> 7, k = idx & 127;
            int n = n0 + i;
            float v = 0.f;
            if (n < N_NODES)
                v = p ? feat[(size_t)n * 128 + k]
                      : __half2float(g_agg_h[(size_t)n * 128 + k]);
            As[i * SA + k] = __uint_as_float(f2tf32(v));
        }
        for (int kt = 0; kt < 8; kt++) {
            __syncthreads();
            for (int idx = tid; idx < 2048; idx += 256) {
                int n = idx >> 4, k = idx & 15;
                Bs[n * SB + k] = __uint_as_float(f2tf32(W[n * 128 + kt * 16 + k]));
            }
            __syncthreads();
#pragma unroll
            for (int ks = 0; ks < 2; ks++) {
                int kb = kt * 16 + ks * 8;
                int ar = rw * 16 + g;
                uint32_t a0 = __float_as_uint(As[ar * SA + kb + t]);
                uint32_t a1 = __float_as_uint(As[(ar + 8) * SA + kb + t]);
                uint32_t a2 = __float_as_uint(As[ar * SA + kb + 4 + t]);
                uint32_t a3 = __float_as_uint(As[(ar + 8) * SA + kb + 4 + t]);
#pragma unroll
                for (int j = 0; j < 8; j++) {
                    int bn = cw * 64 + j * 8 + g;
                    uint32_t b0 = __float_as_uint(Bs[bn * SB + ks * 8 + t]);
                    uint32_t b1 = __float_as_uint(Bs[bn * SB + ks * 8 + 4 + t]);
                    mma_tf32(acc[j], a0, a1, a2, a3, b0, b1);
                }
            }
        }
    }

    // ---- epilogue: relu * mask1 * mask2 -> H (tf32) into As ----
    __syncthreads();
    {
        int r0 = rw * 16 + g, r1 = r0 + 8;
        int nA = n0 + r0, nB = n0 + r1;
#pragma unroll
        for (int j = 0; j < 8; j++) {
            int col = cw * 64 + j * 8 + 2 * t;
            float2 z = make_float2(0.f, 0.f);
            float2 m1a = z, m2a = z, m1b = z, m2b = z;
            if (nA < N_NODES) {
                m1a = *(const float2*)&mask1[(size_t)nA * 128 + col];
                m2a = *(const float2*)&mask2[(size_t)nA * 128 + col];
            }
            if (nB < N_NODES) {
                m1b = *(const float2*)&mask1[(size_t)nB * 128 + col];
                m2b = *(const float2*)&mask2[(size_t)nB * 128 + col];
            }
            float h0 = fmaxf(acc[j][0], 0.f) * m1a.x * m2a.x;
            float h1 = fmaxf(acc[j][1], 0.f) * m1a.y * m2a.y;
            float h2v = fmaxf(acc[j][2], 0.f) * m1b.x * m2b.x;
            float h3 = fmaxf(acc[j][3], 0.f) * m1b.y * m2b.y;
            As[r0 * SA + col] = __uint_as_float(f2tf32(h0));
            As[r0 * SA + col + 1] = __uint_as_float(f2tf32(h1));
            As[r1 * SA + col] = __uint_as_float(f2tf32(h2v));
            As[r1 * SA + col + 1] = __uint_as_float(f2tf32(h3));
        }
    }

    // ---- stage 2: h2 = H @ W_out^T (64 out cols), store fp16 ----
    float acc2[4][4];
#pragma unroll
    for (int j = 0; j < 4; j++)
#pragma unroll
        for (int q = 0; q < 4; q++) acc2[j][q] = 0.f;

    for (int kt = 0; kt < 8; kt++) {
        __syncthreads();
        for (int idx = tid; idx < 1024; idx += 256) {
            int n = idx >> 4, k = idx & 15;
            Bs[n * SB + k] = __uint_as_float(f2tf32(W_out[n * 128 + kt * 16 + k]));
        }
        __syncthreads();
#pragma unroll
        for (int ks = 0; ks < 2; ks++) {
            int kb = kt * 16 + ks * 8;
            int ar = rw * 16 + g;
            uint32_t a0 = __float_as_uint(As[ar * SA + kb + t]);
            uint32_t a1 = __float_as_uint(As[(ar + 8) * SA + kb + t]);
            uint32_t a2 = __float_as_uint(As[ar * SA + kb + 4 + t]);
            uint32_t a3 = __float_as_uint(As[(ar + 8) * SA + kb + 4 + t]);
#pragma unroll
            for (int j = 0; j < 4; j++) {
                int bn = cw * 32 + j * 8 + g;
                uint32_t b0 = __float_as_uint(Bs[bn * SB + ks * 8 + t]);
                uint32_t b1 = __float_as_uint(Bs[bn * SB + ks * 8 + 4 + t]);
                mma_tf32(acc2[j], a0, a1, a2, a3, b0, b1);
            }
        }
    }

    {
        int r0 = rw * 16 + g;
        int nA = n0 + r0, nB = nA + 8;
#pragma unroll
        for (int j = 0; j < 4; j++) {
            int col = cw * 32 + j * 8 + 2 * t;
            if (nA < N_NODES)
                *(half2*)&g_h2h[(size_t)nA * 64 + col] =
                    __floats2half2_rn(acc2[j][0], acc2[j][1]);
            if (nB < N_NODES)
                *(half2*)&g_h2h[(size_t)nB * 64 + col] =
                    __floats2half2_rn(acc2[j][2], acc2[j][3]);
        }
    }
}

// ---------------- 7. out[src] = sum h2[dst] : fp16 gather ------------------
// warp per src node; lane covers out cols 2*lane, 2*lane+1 (one half2)
__global__ void k_out(float* __restrict__ out) {
    int w = (blockIdx.x * blockDim.x + threadIdx.x) >> 5;
    if (w >= N_NODES) return;
    int lane = threadIdx.x & 31;
    int beg = g_off_s[w], end = g_off_s[w + 1];
    const uint32_t* H = (const uint32_t*)g_h2h;   // row = 32 uint (64 halves)
    float ax = 0.f, ay = 0.f;
    int j = beg;
    for (; j + 4 <= end; j += 4) {
        int d0 = g_adj_s[j + 0];
        int d1 = g_adj_s[j + 1];
        int d2 = g_adj_s[j + 2];
        int d3 = g_adj_s[j + 3];
        uint32_t v0 = H[(size_t)d0 * 32 + lane];
        uint32_t v1 = H[(size_t)d1 * 32 + lane];
        uint32_t v2 = H[(size_t)d2 * 32 + lane];
        uint32_t v3 = H[(size_t)d3 * 32 + lane];
        float2 f0 = __half22float2(*(half2*)&v0);
        float2 f1 = __half22float2(*(half2*)&v1);
        float2 f2 = __half22float2(*(half2*)&v2);
        float2 f3 = __half22float2(*(half2*)&v3);
        ax += f0.x + f1.x + f2.x + f3.x;
        ay += f0.y + f1.y + f2.y + f3.y;
    }
    for (; j < end; j++) {
        int d0 = g_adj_s[j];
        uint32_t v0 = H[(size_t)d0 * 32 + lane];
        float2 f0 = __half22float2(*(half2*)&v0);
        ax += f0.x; ay += f0.y;
    }
    ((float2*)out)[(size_t)w * 32 + lane] = make_float2(ax, ay);
}

// ---------------- launch ----------------------------------------------------
extern "C" void kernel_launch(void* const* d_in, const int* in_sizes, int n_in,
                              void* d_out, int out_size) {
    const float* feat = (const float*)d_in[0];
    const int* ei = (const int*)d_in[1];
    const float* W_l = (const float*)d_in[2];
    const float* W_r = (const float*)d_in[3];
    const float* W_out = (const float*)d_in[4];
    const float* mask1 = (const float*)d_in[5];
    const float* mask2 = (const float*)d_in[6];
    float* out = (float*)d_out;

    k_zero<<<256, 256>>>();
    k_feat16<<<(N_NODES * FEAT / 2 + 255) / 256, 256>>>(feat);
    k_count<<<(N_EDGES / 4 + 255) / 256, 256>>>(ei);
    k_scan1<<<2 * NCHUNK, 1024>>>();
    k_scan2<<<1, 256>>>();
    k_scan3<<<2 * NCHUNK, 1024>>>();
    k_fill<<<(N_EDGES / 4 + 255) / 256, 256>>>(ei);
    k_aggregate<<<(N_NODES * 32 + 255) / 256, 256>>>();
    k_mlp<<<(N_NODES + 63) / 64, 256>>>(feat, W_l, W_r, W_out, mask1, mask2);
    k_out<<<(N_NODES * 32 + 255) / 256, 256>>>(out);
}

// round 5
// speedup vs baseline: 1.1070x; 1.1070x over previous
#include <cuda_runtime.h>
#include <cuda_fp16.h>
#include <cstdint>

#define N_NODES 100000
#define N_EDGES 3200000
#define FEAT 128
#define HID 128
#define NCLS 64
#define NCHUNK 98              // ceil(100000/1024)
#define FEAT4_BLOCKS 12500     // N_NODES*FEAT/4 / 256
#define CNT_BLOCKS 3125        // N_EDGES/4 / 256

// ---------------- scratch (device globals: no allocation allowed) ----------
__device__ int g_cnt_d[N_NODES];
__device__ int g_cnt_s[N_NODES];
__device__ int g_off_d[N_NODES + 1];
__device__ int g_off_s[N_NODES + 1];
__device__ int g_cur_d[N_NODES];
__device__ int g_cur_s[N_NODES];
__device__ int g_chk[2 * NCHUNK];
__device__ int g_adj_d[N_EDGES];   // src ids bucketed by dst
__device__ int g_adj_s[N_EDGES];   // dst ids bucketed by src
__device__ __half g_feat_h[(size_t)N_NODES * FEAT];  // fp16 features
__device__ __half g_agg_h[(size_t)N_NODES * FEAT];   // fp16 mean-aggregated
__device__ __half g_h2h[(size_t)N_NODES * NCLS];     // fp16 post-W_out hidden

// ---------------- 1. fused: feat->fp16 (blocks 0..12499) + degree count ----
__global__ void k_pre(const float* __restrict__ feat, const int* __restrict__ ei) {
    int bx = blockIdx.x;
    int tid = threadIdx.x;
    if (bx < FEAT4_BLOCKS) {
        int i = bx * 256 + tid;                 // one float4 -> 2x half2
        float4 v = ((const float4*)feat)[i];
        uint2 r;
        *(half2*)&r.x = __floats2half2_rn(v.x, v.y);
        *(half2*)&r.y = __floats2half2_rn(v.z, v.w);
        ((uint2*)g_feat_h)[i] = r;
    } else {
        int i = (bx - FEAT4_BLOCKS) * 256 + tid;
        if (i >= N_EDGES / 4) return;
        int4 s4 = ((const int4*)ei)[i];
        int4 d4 = ((const int4*)(ei + N_EDGES))[i];
        atomicAdd(&g_cnt_s[s4.x], 1);
        atomicAdd(&g_cnt_s[s4.y], 1);
        atomicAdd(&g_cnt_s[s4.z], 1);
        atomicAdd(&g_cnt_s[s4.w], 1);
        atomicAdd(&g_cnt_d[d4.x], 1);
        atomicAdd(&g_cnt_d[d4.y], 1);
        atomicAdd(&g_cnt_d[d4.z], 1);
        atomicAdd(&g_cnt_d[d4.w], 1);
    }
}

// ---------------- 2. parallel exclusive scan (3 phases) --------------------
__global__ void k_scan1() {
    __shared__ int wsum[32];
    int bx = blockIdx.x;
    int sel = bx >= NCHUNK ? 1 : 0;
    int chunk = bx - sel * NCHUNK;
    const int* cnt = sel ? g_cnt_s : g_cnt_d;
    int* off = sel ? g_off_s : g_off_d;
    int tid = threadIdx.x, lane = tid & 31, wid = tid >> 5;
    int i = chunk * 1024 + tid;
    int v = (i < N_NODES) ? cnt[i] : 0;
    int x = v;
#pragma unroll
    for (int o = 1; o < 32; o <<= 1) {
        int y = __shfl_up_sync(0xffffffffu, x, o);
        if (lane >= o) x += y;
    }
    if (lane == 31) wsum[wid] = x;
    __syncthreads();
    if (wid == 0) {
        int xx = wsum[lane];
#pragma unroll
        for (int o = 1; o < 32; o <<= 1) {
            int y = __shfl_up_sync(0xffffffffu, xx, o);
            if (lane >= o) xx += y;
        }
        wsum[lane] = xx;
    }
    __syncthreads();
    int excl = x - v + (wid > 0 ? wsum[wid - 1] : 0);
    if (i < N_NODES) off[i] = excl;
    if (tid == 1023) g_chk[sel * NCHUNK + chunk] = wsum[31];
}

__global__ void k_scan2() {
    __shared__ int sh[256];
    int tid = threadIdx.x;
    int sel = tid >> 7, idx = tid & 127;
    int v = (idx < NCHUNK) ? g_chk[sel * NCHUNK + idx] : 0;
    sh[tid] = v;
    __syncthreads();
#pragma unroll
    for (int o = 1; o < 128; o <<= 1) {
        int y = (idx >= o) ? sh[tid - o] : 0;
        __syncthreads();
        sh[tid] += y;
        __syncthreads();
    }
    if (idx < NCHUNK) g_chk[sel * NCHUNK + idx] = sh[tid] - v;  // exclusive
    if (tid == 0) {
        g_off_d[N_NODES] = N_EDGES;
        g_off_s[N_NODES] = N_EDGES;
    }
}

__global__ void k_scan3() {
    int bx = blockIdx.x;
    int sel = bx >= NCHUNK ? 1 : 0;
    int chunk = bx - sel * NCHUNK;
    int i = chunk * 1024 + threadIdx.x;
    if (i >= N_NODES) return;
    int add = g_chk[sel * NCHUNK + chunk];
    if (sel) {
        int p = g_off_s[i] + add;
        g_off_s[i] = p;
        g_cur_s[i] = p;
    } else {
        int p = g_off_d[i] + add;
        g_off_d[i] = p;
        g_cur_d[i] = p;
    }
}

// ---------------- 3. fill CSR buckets (4 edges/thread) ---------------------
__global__ void k_fill(const int* __restrict__ ei) {
    int i = blockIdx.x * blockDim.x + threadIdx.x;
    if (i >= N_EDGES / 4) return;
    int4 s4 = ((const int4*)ei)[i];
    int4 d4 = ((const int4*)(ei + N_EDGES))[i];
    int p0 = atomicAdd(&g_cur_d[d4.x], 1);
    int p1 = atomicAdd(&g_cur_d[d4.y], 1);
    int p2 = atomicAdd(&g_cur_d[d4.z], 1);
    int p3 = atomicAdd(&g_cur_d[d4.w], 1);
    g_adj_d[p0] = s4.x;
    g_adj_d[p1] = s4.y;
    g_adj_d[p2] = s4.z;
    g_adj_d[p3] = s4.w;
    int q0 = atomicAdd(&g_cur_s[s4.x], 1);
    int q1 = atomicAdd(&g_cur_s[s4.y], 1);
    int q2 = atomicAdd(&g_cur_s[s4.z], 1);
    int q3 = atomicAdd(&g_cur_s[s4.w], 1);
    g_adj_s[q0] = d4.x;
    g_adj_s[q1] = d4.y;
    g_adj_s[q2] = d4.z;
    g_adj_s[q3] = d4.w;
}

// ---------------- 4. mean aggregation: HALF-WARP per node ------------------
// fp16 row = 256B = 16 lanes x uint4 (LDG.128). 8-edge unroll -> 16 LDG.128
// in flight per warp. fp32 accumulate.
__device__ __forceinline__ void acc_u4(float* a, uint4 v) {
    float2 p0 = __half22float2(*(half2*)&v.x);
    float2 p1 = __half22float2(*(half2*)&v.y);
    float2 p2 = __half22float2(*(half2*)&v.z);
    float2 p3 = __half22float2(*(half2*)&v.w);
    a[0] += p0.x; a[1] += p0.y; a[2] += p1.x; a[3] += p1.y;
    a[4] += p2.x; a[5] += p2.y; a[6] += p3.x; a[7] += p3.y;
}

__global__ void k_aggregate() {
    int t = blockIdx.x * blockDim.x + threadIdx.x;
    int node = t >> 4;
    if (node >= N_NODES) return;
    int lane = threadIdx.x & 15;
    int beg = g_off_d[node], end = g_off_d[node + 1];
    const uint4* F = (const uint4*)g_feat_h;   // row = 16 uint4
    float a[8] = {0.f, 0.f, 0.f, 0.f, 0.f, 0.f, 0.f, 0.f};
    int j = beg;
    for (; j + 8 <= end; j += 8) {
        int s[8];
#pragma unroll
        for (int e = 0; e < 8; e++) s[e] = g_adj_d[j + e];
        uint4 v[8];
#pragma unroll
        for (int e = 0; e < 8; e++) v[e] = F[(size_t)s[e] * 16 + lane];
#pragma unroll
        for (int e = 0; e < 8; e++) acc_u4(a, v[e]);
    }
    for (; j < end; j++) {
        uint4 v = F[(size_t)g_adj_d[j] * 16 + lane];
        acc_u4(a, v);
    }
    float inv = (end > beg) ? 1.0f / (float)(end - beg) : 0.0f;
    uint4 r;
    *(half2*)&r.x = __floats2half2_rn(a[0] * inv, a[1] * inv);
    *(half2*)&r.y = __floats2half2_rn(a[2] * inv, a[3] * inv);
    *(half2*)&r.z = __floats2half2_rn(a[4] * inv, a[5] * inv);
    *(half2*)&r.w = __floats2half2_rn(a[6] * inv, a[7] * inv);
    ((uint4*)g_agg_h)[(size_t)node * 16 + lane] = r;
}

// ---------------- 5. fused MLP on tensor cores (tf32 mma.sync) -------------
#define SA 132
#define SB 20

__device__ __forceinline__ uint32_t f2tf32(float v) {
    uint32_t u;
    asm("cvt.rna.tf32.f32 %0, %1;" : "=r"(u) : "f"(v));
    return u;
}

__device__ __forceinline__ void mma_tf32(float c[4], uint32_t a0, uint32_t a1,
                                         uint32_t a2, uint32_t a3,
                                         uint32_t b0, uint32_t b1) {
    asm volatile(
        "mma.sync.aligned.m16n8k8.row.col.f32.tf32.tf32.f32 "
        "{%0,%1,%2,%3}, {%4,%5,%6,%7}, {%8,%9}, {%0,%1,%2,%3};"
        : "+f"(c[0]), "+f"(c[1]), "+f"(c[2]), "+f"(c[3])
        : "r"(a0), "r"(a1), "r"(a2), "r"(a3), "r"(b0), "r"(b1));
}

__global__ __launch_bounds__(256) void k_mlp(
    const float* __restrict__ feat,
    const float* __restrict__ W_l, const float* __restrict__ W_r,
    const float* __restrict__ W_out,
    const float* __restrict__ mask1, const float* __restrict__ mask2) {
    __shared__ __align__(16) float As[64 * SA];
    __shared__ __align__(16) float Bs[128 * SB];

    int tid = threadIdx.x;
    int lane = tid & 31, w = tid >> 5;
    int rw = w & 3, cw = w >> 2;
    int g = lane >> 2, t = lane & 3;
    int n0 = blockIdx.x * 64;

    float acc[8][4];
#pragma unroll
    for (int j = 0; j < 8; j++)
#pragma unroll
        for (int q = 0; q < 4; q++) acc[j][q] = 0.f;

    // ---- stage 1: pass 0 = agg(fp16)@W_l, pass 1 = feat(fp32)@W_r ----
    for (int p = 0; p < 2; p++) {
        const float* W = p ? W_r : W_l;
        __syncthreads();
        for (int idx = tid; idx < 64 * 128; idx += 256) {
            int i = idx >> 7, k = idx & 127;
            int n = n0 + i;
            float v = 0.f;
            if (n < N_NODES)
                v = p ? feat[(size_t)n * 128 + k]
                      : __half2float(g_agg_h[(size_t)n * 128 + k]);
            As[i * SA + k] = __uint_as_float(f2tf32(v));
        }
        for (int kt = 0; kt < 8; kt++) {
            __syncthreads();
            for (int idx = tid; idx < 2048; idx += 256) {
                int n = idx >> 4, k = idx & 15;
                Bs[n * SB + k] = __uint_as_float(f2tf32(W[n * 128 + kt * 16 + k]));
            }
            __syncthreads();
#pragma unroll
            for (int ks = 0; ks < 2; ks++) {
                int kb = kt * 16 + ks * 8;
                int ar = rw * 16 + g;
                uint32_t a0 = __float_as_uint(As[ar * SA + kb + t]);
                uint32_t a1 = __float_as_uint(As[(ar + 8) * SA + kb + t]);
                uint32_t a2 = __float_as_uint(As[ar * SA + kb + 4 + t]);
                uint32_t a3 = __float_as_uint(As[(ar + 8) * SA + kb + 4 + t]);
#pragma unroll
                for (int j = 0; j < 8; j++) {
                    int bn = cw * 64 + j * 8 + g;
                    uint32_t b0 = __float_as_uint(Bs[bn * SB + ks * 8 + t]);
                    uint32_t b1 = __float_as_uint(Bs[bn * SB + ks * 8 + 4 + t]);
                    mma_tf32(acc[j], a0, a1, a2, a3, b0, b1);
                }
            }
        }
    }

    // ---- epilogue: relu * mask1 * mask2 -> H (tf32) into As ----
    __syncthreads();
    {
        int r0 = rw * 16 + g, r1 = r0 + 8;
        int nA = n0 + r0, nB = n0 + r1;
#pragma unroll
        for (int j = 0; j < 8; j++) {
            int col = cw * 64 + j * 8 + 2 * t;
            float2 z = make_float2(0.f, 0.f);
            float2 m1a = z, m2a = z, m1b = z, m2b = z;
            if (nA < N_NODES) {
                m1a = *(const float2*)&mask1[(size_t)nA * 128 + col];
                m2a = *(const float2*)&mask2[(size_t)nA * 128 + col];
            }
            if (nB < N_NODES) {
                m1b = *(const float2*)&mask1[(size_t)nB * 128 + col];
                m2b = *(const float2*)&mask2[(size_t)nB * 128 + col];
            }
            float h0 = fmaxf(acc[j][0], 0.f) * m1a.x * m2a.x;
            float h1 = fmaxf(acc[j][1], 0.f) * m1a.y * m2a.y;
            float h2v = fmaxf(acc[j][2], 0.f) * m1b.x * m2b.x;
            float h3 = fmaxf(acc[j][3], 0.f) * m1b.y * m2b.y;
            As[r0 * SA + col] = __uint_as_float(f2tf32(h0));
            As[r0 * SA + col + 1] = __uint_as_float(f2tf32(h1));
            As[r1 * SA + col] = __uint_as_float(f2tf32(h2v));
            As[r1 * SA + col + 1] = __uint_as_float(f2tf32(h3));
        }
    }

    // ---- stage 2: h2 = H @ W_out^T (64 out cols), store fp16 ----
    float acc2[4][4];
#pragma unroll
    for (int j = 0; j < 4; j++)
#pragma unroll
        for (int q = 0; q < 4; q++) acc2[j][q] = 0.f;

    for (int kt = 0; kt < 8; kt++) {
        __syncthreads();
        for (int idx = tid; idx < 1024; idx += 256) {
            int n = idx >> 4, k = idx & 15;
            Bs[n * SB + k] = __uint_as_float(f2tf32(W_out[n * 128 + kt * 16 + k]));
        }
        __syncthreads();
#pragma unroll
        for (int ks = 0; ks < 2; ks++) {
            int kb = kt * 16 + ks * 8;
            int ar = rw * 16 + g;
            uint32_t a0 = __float_as_uint(As[ar * SA + kb + t]);
            uint32_t a1 = __float_as_uint(As[(ar + 8) * SA + kb + t]);
            uint32_t a2 = __float_as_uint(As[ar * SA + kb + 4 + t]);
            uint32_t a3 = __float_as_uint(As[(ar + 8) * SA + kb + 4 + t]);
#pragma unroll
            for (int j = 0; j < 4; j++) {
                int bn = cw * 32 + j * 8 + g;
                uint32_t b0 = __float_as_uint(Bs[bn * SB + ks * 8 + t]);
                uint32_t b1 = __float_as_uint(Bs[bn * SB + ks * 8 + 4 + t]);
                mma_tf32(acc2[j], a0, a1, a2, a3, b0, b1);
            }
        }
    }

    {
        int r0 = rw * 16 + g;
        int nA = n0 + r0, nB = nA + 8;
#pragma unroll
        for (int j = 0; j < 4; j++) {
            int col = cw * 32 + j * 8 + 2 * t;
            if (nA < N_NODES)
                *(half2*)&g_h2h[(size_t)nA * 64 + col] =
                    __floats2half2_rn(acc2[j][0], acc2[j][1]);
            if (nB < N_NODES)
                *(half2*)&g_h2h[(size_t)nB * 64 + col] =
                    __floats2half2_rn(acc2[j][2], acc2[j][3]);
        }
    }
}

// ---------------- 6. out[src] = sum h2[dst] : QUARTER-WARP per node --------
// fp16 row = 128B = 8 lanes x uint4. 4-edge unroll -> 16 LDG.128 per warp.
__global__ void k_out(float* __restrict__ out) {
    int t = blockIdx.x * blockDim.x + threadIdx.x;
    int node = t >> 3;
    if (node >= N_NODES) return;
    int lane = threadIdx.x & 7;
    int beg = g_off_s[node], end = g_off_s[node + 1];
    const uint4* H = (const uint4*)g_h2h;      // row = 8 uint4
    float a[8] = {0.f, 0.f, 0.f, 0.f, 0.f, 0.f, 0.f, 0.f};
    int j = beg;
    for (; j + 4 <= end; j += 4) {
        int d[4];
#pragma unroll
        for (int e = 0; e < 4; e++) d[e] = g_adj_s[j + e];
        uint4 v[4];
#pragma unroll
        for (int e = 0; e < 4; e++) v[e] = H[(size_t)d[e] * 8 + lane];
#pragma unroll
        for (int e = 0; e < 4; e++) acc_u4(a, v[e]);
    }
    for (; j < end; j++) {
        uint4 v = H[(size_t)g_adj_s[j] * 8 + lane];
        acc_u4(a, v);
    }
    float4* O = (float4*)out;                  // row = 16 float4
    O[(size_t)node * 16 + lane * 2] = make_float4(a[0], a[1], a[2], a[3]);
    O[(size_t)node * 16 + lane * 2 + 1] = make_float4(a[4], a[5], a[6], a[7]);
}

// ---------------- launch ----------------------------------------------------
extern "C" void kernel_launch(void* const* d_in, const int* in_sizes, int n_in,
                              void* d_out, int out_size) {
    const float* feat = (const float*)d_in[0];
    const int* ei = (const int*)d_in[1];
    const float* W_l = (const float*)d_in[2];
    const float* W_r = (const float*)d_in[3];
    const float* W_out = (const float*)d_in[4];
    const float* mask1 = (const float*)d_in[5];
    const float* mask2 = (const float*)d_in[6];
    float* out = (float*)d_out;

    void *p_cd = nullptr, *p_cs = nullptr;
    cudaGetSymbolAddress(&p_cd, g_cnt_d);
    cudaGetSymbolAddress(&p_cs, g_cnt_s);
    cudaMemsetAsync(p_cd, 0, N_NODES * sizeof(int));
    cudaMemsetAsync(p_cs, 0, N_NODES * sizeof(int));

    k_pre<<<FEAT4_BLOCKS + CNT_BLOCKS, 256>>>(feat, ei);
    k_scan1<<<2 * NCHUNK, 1024>>>();
    k_scan2<<<1, 256>>>();
    k_scan3<<<2 * NCHUNK, 1024>>>();
    k_fill<<<(N_EDGES / 4 + 255) / 256, 256>>>(ei);
    k_aggregate<<<(N_NODES * 16 + 255) / 256, 256>>>();
    k_mlp<<<(N_NODES + 63) / 64, 256>>>(feat, W_l, W_r, W_out, mask1, mask2);
    k_out<<<(N_NODES * 8 + 255) / 256, 256>>>(out);
}

// round 6
// speedup vs baseline: 1.1543x; 1.0427x over previous
#include <cuda_runtime.h>
#include <cuda_fp16.h>
#include <cstdint>

#define N_NODES 100000
#define N_EDGES 3200000
#define FEAT 128
#define HID 128
#define NCLS 64
#define NCHUNK 98              // ceil(100000/1024)
#define FEAT4_BLOCKS 12500     // N_NODES*FEAT/4 / 256
#define CNT_BLOCKS 3125        // N_EDGES/4 / 256
#define MLP_BLOCKS 1563        // ceil(N_NODES/64)
#define FILLS_BLOCKS 3125      // N_EDGES/4 / 256

// ---------------- scratch (device globals: no allocation allowed) ----------
__device__ int g_cnt_d[N_NODES];
__device__ int g_cnt_s[N_NODES];
__device__ int g_off_d[N_NODES + 1];
__device__ int g_off_s[N_NODES + 1];
__device__ int g_cur_d[N_NODES];
__device__ int g_cur_s[N_NODES];
__device__ int g_chk[2 * NCHUNK];
__device__ int g_adj_d[N_EDGES];   // src ids bucketed by dst
__device__ int g_adj_s[N_EDGES];   // dst ids bucketed by src
__device__ __half g_feat_h[(size_t)N_NODES * FEAT];  // fp16 features
__device__ __half g_h2h[(size_t)N_NODES * NCLS];     // fp16 post-W_out hidden

// ---------------- 1. fused: feat->fp16 (blocks 0..12499) + degree count ----
__global__ void k_pre(const float* __restrict__ feat, const int* __restrict__ ei) {
    int bx = blockIdx.x;
    int tid = threadIdx.x;
    if (bx < FEAT4_BLOCKS) {
        int i = bx * 256 + tid;                 // one float4 -> 2x half2
        float4 v = ((const float4*)feat)[i];
        uint2 r;
        *(half2*)&r.x = __floats2half2_rn(v.x, v.y);
        *(half2*)&r.y = __floats2half2_rn(v.z, v.w);
        ((uint2*)g_feat_h)[i] = r;
    } else {
        int i = (bx - FEAT4_BLOCKS) * 256 + tid;
        int4 s4 = ((const int4*)ei)[i];
        int4 d4 = ((const int4*)(ei + N_EDGES))[i];
        atomicAdd(&g_cnt_s[s4.x], 1);
        atomicAdd(&g_cnt_s[s4.y], 1);
        atomicAdd(&g_cnt_s[s4.z], 1);
        atomicAdd(&g_cnt_s[s4.w], 1);
        atomicAdd(&g_cnt_d[d4.x], 1);
        atomicAdd(&g_cnt_d[d4.y], 1);
        atomicAdd(&g_cnt_d[d4.z], 1);
        atomicAdd(&g_cnt_d[d4.w], 1);
    }
}

// ---------------- 2. scan phase 1: per-chunk local scan + chunk totals -----
__global__ void k_scan1() {
    __shared__ int wsum[32];
    int bx = blockIdx.x;
    int sel = bx >= NCHUNK ? 1 : 0;
    int chunk = bx - sel * NCHUNK;
    const int* cnt = sel ? g_cnt_s : g_cnt_d;
    int* off = sel ? g_off_s : g_off_d;
    int tid = threadIdx.x, lane = tid & 31, wid = tid >> 5;
    int i = chunk * 1024 + tid;
    int v = (i < N_NODES) ? cnt[i] : 0;
    int x = v;
#pragma unroll
    for (int o = 1; o < 32; o <<= 1) {
        int y = __shfl_up_sync(0xffffffffu, x, o);
        if (lane >= o) x += y;
    }
    if (lane == 31) wsum[wid] = x;
    __syncthreads();
    if (wid == 0) {
        int xx = wsum[lane];
#pragma unroll
        for (int o = 1; o < 32; o <<= 1) {
            int y = __shfl_up_sync(0xffffffffu, xx, o);
            if (lane >= o) xx += y;
        }
        wsum[lane] = xx;
    }
    __syncthreads();
    int excl = x - v + (wid > 0 ? wsum[wid - 1] : 0);
    if (i < N_NODES) off[i] = excl;
    if (tid == 1023) g_chk[sel * NCHUNK + chunk] = wsum[31];   // raw total
}

// ---------------- 3. scan phase 2+3 fused: add chunk prefix, init cursors --
__global__ void k_scan3() {
    __shared__ int red[128];
    int bx = blockIdx.x;
    int sel = bx >= NCHUNK ? 1 : 0;
    int chunk = bx - sel * NCHUNK;
    int tid = threadIdx.x;
    if (tid < 128)
        red[tid] = (tid < chunk) ? g_chk[sel * NCHUNK + tid] : 0;
    __syncthreads();
#pragma unroll
    for (int o = 64; o > 0; o >>= 1) {
        if (tid < o) red[tid] += red[tid + o];
        __syncthreads();
    }
    int add = red[0];
    int i = chunk * 1024 + tid;
    if (i < N_NODES) {
        if (sel) {
            int p = g_off_s[i] + add;
            g_off_s[i] = p;
            g_cur_s[i] = p;
        } else {
            int p = g_off_d[i] + add;
            g_off_d[i] = p;
            g_cur_d[i] = p;
        }
    }
    if (bx == 0 && tid == 0) {
        g_off_d[N_NODES] = N_EDGES;
        g_off_s[N_NODES] = N_EDGES;
    }
}

// ---------------- 4. fill dst-side CSR only (4 edges/thread) ---------------
__global__ void k_fill_d(const int* __restrict__ ei) {
    int i = blockIdx.x * blockDim.x + threadIdx.x;
    int4 s4 = ((const int4*)ei)[i];
    int4 d4 = ((const int4*)(ei + N_EDGES))[i];
    int p0 = atomicAdd(&g_cur_d[d4.x], 1);
    int p1 = atomicAdd(&g_cur_d[d4.y], 1);
    int p2 = atomicAdd(&g_cur_d[d4.z], 1);
    int p3 = atomicAdd(&g_cur_d[d4.w], 1);
    g_adj_d[p0] = s4.x;
    g_adj_d[p1] = s4.y;
    g_adj_d[p2] = s4.z;
    g_adj_d[p3] = s4.w;
}

// ---------------- helpers ---------------------------------------------------
__device__ __forceinline__ void acc_u4(float* a, uint4 v) {
    float2 p0 = __half22float2(*(half2*)&v.x);
    float2 p1 = __half22float2(*(half2*)&v.y);
    float2 p2 = __half22float2(*(half2*)&v.z);
    float2 p3 = __half22float2(*(half2*)&v.w);
    a[0] += p0.x; a[1] += p0.y; a[2] += p1.x; a[3] += p1.y;
    a[4] += p2.x; a[5] += p2.y; a[6] += p3.x; a[7] += p3.y;
}

__device__ __forceinline__ uint32_t f2tf32(float v) {
    uint32_t u;
    asm("cvt.rna.tf32.f32 %0, %1;" : "=r"(u) : "f"(v));
    return u;
}
__device__ __forceinline__ float tf32f(float v) {
    return __uint_as_float(f2tf32(v));
}

__device__ __forceinline__ void mma_tf32(float c[4], uint32_t a0, uint32_t a1,
                                         uint32_t a2, uint32_t a3,
                                         uint32_t b0, uint32_t b1) {
    asm volatile(
        "mma.sync.aligned.m16n8k8.row.col.f32.tf32.tf32.f32 "
        "{%0,%1,%2,%3}, {%4,%5,%6,%7}, {%8,%9}, {%0,%1,%2,%3};"
        : "+f"(c[0]), "+f"(c[1]), "+f"(c[2]), "+f"(c[3])
        : "r"(a0), "r"(a1), "r"(a2), "r"(a3), "r"(b0), "r"(b1));
}

// ---------------- 5. FUSED: aggregate + MLP (+ src-side fill riders) -------
// Blocks [0, MLP_BLOCKS): 64-node tile. Phase A gathers+means neighbor feats
// straight into As (tf32). Then tf32 MMA stage1 (W_l on agg, W_r on feat),
// mask epilogue, stage2 (W_out) -> fp16 g_h2h.
// Blocks [MLP_BLOCKS, +FILLS_BLOCKS): fill src-side CSR (needed only by k_out).
#define SA 132
#define SB 20

__global__ __launch_bounds__(256) void k_mlp(
    const float* __restrict__ W_l, const float* __restrict__ W_r,
    const float* __restrict__ W_out,
    const float* __restrict__ mask1, const float* __restrict__ mask2,
    const int* __restrict__ ei) {
    __shared__ __align__(16) float As[64 * SA];
    __shared__ __align__(16) float Bs[128 * SB];

    int tid = threadIdx.x;

    if (blockIdx.x >= MLP_BLOCKS) {
        // ---- rider: fill src-side CSR (4 edges/thread) ----
        int i = (blockIdx.x - MLP_BLOCKS) * 256 + tid;
        int4 s4 = ((const int4*)ei)[i];
        int4 d4 = ((const int4*)(ei + N_EDGES))[i];
        int q0 = atomicAdd(&g_cur_s[s4.x], 1);
        int q1 = atomicAdd(&g_cur_s[s4.y], 1);
        int q2 = atomicAdd(&g_cur_s[s4.z], 1);
        int q3 = atomicAdd(&g_cur_s[s4.w], 1);
        g_adj_s[q0] = d4.x;
        g_adj_s[q1] = d4.y;
        g_adj_s[q2] = d4.z;
        g_adj_s[q3] = d4.w;
        return;
    }

    int lane = tid & 31, w = tid >> 5;
    int rw = w & 3, cw = w >> 2;
    int g = lane >> 2, t = lane & 3;
    int n0 = blockIdx.x * 64;
    const uint4* Fh = (const uint4*)g_feat_h;   // fp16 row = 16 uint4

    // ---- phase A: mean-aggregate this block's 64 nodes into As (tf32) ----
    {
        int grp = tid >> 4;        // 16 threads per node
        int l16 = tid & 15;
#pragma unroll
        for (int pass = 0; pass < 4; pass++) {
            int il = pass * 16 + grp;
            int node = n0 + il;
            float a[8] = {0.f, 0.f, 0.f, 0.f, 0.f, 0.f, 0.f, 0.f};
            int beg = 0, end = 0;
            if (node < N_NODES) {
                beg = g_off_d[node];
                end = g_off_d[node + 1];
            }
            int j = beg;
            for (; j + 8 <= end; j += 8) {
                int s[8];
#pragma unroll
                for (int e = 0; e < 8; e++) s[e] = g_adj_d[j + e];
                uint4 v[8];
#pragma unroll
                for (int e = 0; e < 8; e++) v[e] = Fh[(size_t)s[e] * 16 + l16];
#pragma unroll
                for (int e = 0; e < 8; e++) acc_u4(a, v[e]);
            }
            for (; j < end; j++)
                acc_u4(a, Fh[(size_t)g_adj_d[j] * 16 + l16]);
            float inv = (end > beg) ? 1.0f / (float)(end - beg) : 0.0f;
            *(float4*)&As[il * SA + l16 * 8] =
                make_float4(tf32f(a[0] * inv), tf32f(a[1] * inv),
                            tf32f(a[2] * inv), tf32f(a[3] * inv));
            *(float4*)&As[il * SA + l16 * 8 + 4] =
                make_float4(tf32f(a[4] * inv), tf32f(a[5] * inv),
                            tf32f(a[6] * inv), tf32f(a[7] * inv));
        }
    }
    __syncthreads();

    float acc[8][4];
#pragma unroll
    for (int j = 0; j < 8; j++)
#pragma unroll
        for (int q = 0; q < 4; q++) acc[j][q] = 0.f;

    // ---- stage 1: p=0 agg(As)@W_l ; p=1 feat(fp16)@W_r ----
    for (int p = 0; p < 2; p++) {
        const float* W = p ? W_r : W_l;
        if (p == 1) {
            __syncthreads();   // all p=0 MMAs done before As overwrite
            for (int idx = tid; idx < 64 * 16; idx += 256) {
                int i = idx >> 4, kq = idx & 15;
                int n = n0 + i;
                uint4 v = make_uint4(0u, 0u, 0u, 0u);
                if (n < N_NODES) v = Fh[(size_t)n * 16 + kq];
                float2 p0 = __half22float2(*(half2*)&v.x);
                float2 p1 = __half22float2(*(half2*)&v.y);
                float2 p2 = __half22float2(*(half2*)&v.z);
                float2 p3 = __half22float2(*(half2*)&v.w);
                *(float4*)&As[i * SA + kq * 8] =
                    make_float4(tf32f(p0.x), tf32f(p0.y), tf32f(p1.x), tf32f(p1.y));
                *(float4*)&As[i * SA + kq * 8 + 4] =
                    make_float4(tf32f(p2.x), tf32f(p2.y), tf32f(p3.x), tf32f(p3.y));
            }
        }
        for (int kt = 0; kt < 8; kt++) {
            __syncthreads();
            for (int idx = tid; idx < 2048; idx += 256) {
                int n = idx >> 4, k = idx & 15;
                Bs[n * SB + k] = tf32f(W[n * 128 + kt * 16 + k]);
            }
            __syncthreads();
#pragma unroll
            for (int ks = 0; ks < 2; ks++) {
                int kb = kt * 16 + ks * 8;
                int ar = rw * 16 + g;
                uint32_t a0 = __float_as_uint(As[ar * SA + kb + t]);
                uint32_t a1 = __float_as_uint(As[(ar + 8) * SA + kb + t]);
                uint32_t a2 = __float_as_uint(As[ar * SA + kb + 4 + t]);
                uint32_t a3 = __float_as_uint(As[(ar + 8) * SA + kb + 4 + t]);
#pragma unroll
                for (int j = 0; j < 8; j++) {
                    int bn = cw * 64 + j * 8 + g;
                    uint32_t b0 = __float_as_uint(Bs[bn * SB + ks * 8 + t]);
                    uint32_t b1 = __float_as_uint(Bs[bn * SB + ks * 8 + 4 + t]);
                    mma_tf32(acc[j], a0, a1, a2, a3, b0, b1);
                }
            }
        }
    }

    // ---- epilogue: relu * mask1 * mask2 -> H (tf32) into As ----
    __syncthreads();
    {
        int r0 = rw * 16 + g, r1 = r0 + 8;
        int nA = n0 + r0, nB = n0 + r1;
#pragma unroll
        for (int j = 0; j < 8; j++) {
            int col = cw * 64 + j * 8 + 2 * t;
            float2 z = make_float2(0.f, 0.f);
            float2 m1a = z, m2a = z, m1b = z, m2b = z;
            if (nA < N_NODES) {
                m1a = *(const float2*)&mask1[(size_t)nA * 128 + col];
                m2a = *(const float2*)&mask2[(size_t)nA * 128 + col];
            }
            if (nB < N_NODES) {
                m1b = *(const float2*)&mask1[(size_t)nB * 128 + col];
                m2b = *(const float2*)&mask2[(size_t)nB * 128 + col];
            }
            float h0 = fmaxf(acc[j][0], 0.f) * m1a.x * m2a.x;
            float h1 = fmaxf(acc[j][1], 0.f) * m1a.y * m2a.y;
            float h2v = fmaxf(acc[j][2], 0.f) * m1b.x * m2b.x;
            float h3 = fmaxf(acc[j][3], 0.f) * m1b.y * m2b.y;
            As[r0 * SA + col] = tf32f(h0);
            As[r0 * SA + col + 1] = tf32f(h1);
            As[r1 * SA + col] = tf32f(h2v);
            As[r1 * SA + col + 1] = tf32f(h3);
        }
    }

    // ---- stage 2: h2 = H @ W_out^T (64 out cols), store fp16 ----
    float acc2[4][4];
#pragma unroll
    for (int j = 0; j < 4; j++)
#pragma unroll
        for (int q = 0; q < 4; q++) acc2[j][q] = 0.f;

    for (int kt = 0; kt < 8; kt++) {
        __syncthreads();
        for (int idx = tid; idx < 1024; idx += 256) {
            int n = idx >> 4, k = idx & 15;
            Bs[n * SB + k] = tf32f(W_out[n * 128 + kt * 16 + k]);
        }
        __syncthreads();
#pragma unroll
        for (int ks = 0; ks < 2; ks++) {
            int kb = kt * 16 + ks * 8;
            int ar = rw * 16 + g;
            uint32_t a0 = __float_as_uint(As[ar * SA + kb + t]);
            uint32_t a1 = __float_as_uint(As[(ar + 8) * SA + kb + t]);
            uint32_t a2 = __float_as_uint(As[ar * SA + kb + 4 + t]);
            uint32_t a3 = __float_as_uint(As[(ar + 8) * SA + kb + 4 + t]);
#pragma unroll
            for (int j = 0; j < 4; j++) {
                int bn = cw * 32 + j * 8 + g;
                uint32_t b0 = __float_as_uint(Bs[bn * SB + ks * 8 + t]);
                uint32_t b1 = __float_as_uint(Bs[bn * SB + ks * 8 + 4 + t]);
                mma_tf32(acc2[j], a0, a1, a2, a3, b0, b1);
            }
        }
    }

    {
        int r0 = rw * 16 + g;
        int nA = n0 + r0, nB = nA + 8;
#pragma unroll
        for (int j = 0; j < 4; j++) {
            int col = cw * 32 + j * 8 + 2 * t;
            if (nA < N_NODES)
                *(half2*)&g_h2h[(size_t)nA * 64 + col] =
                    __floats2half2_rn(acc2[j][0], acc2[j][1]);
            if (nB < N_NODES)
                *(half2*)&g_h2h[(size_t)nB * 64 + col] =
                    __floats2half2_rn(acc2[j][2], acc2[j][3]);
        }
    }
}

// ---------------- 6. out[src] = sum h2[dst] : QUARTER-WARP per node --------
__global__ void k_out(float* __restrict__ out) {
    int t = blockIdx.x * blockDim.x + threadIdx.x;
    int node = t >> 3;
    if (node >= N_NODES) return;
    int lane = threadIdx.x & 7;
    int beg = g_off_s[node], end = g_off_s[node + 1];
    const uint4* H = (const uint4*)g_h2h;      // row = 8 uint4
    float a[8] = {0.f, 0.f, 0.f, 0.f, 0.f, 0.f, 0.f, 0.f};
    int j = beg;
    for (; j + 4 <= end; j += 4) {
        int d[4];
#pragma unroll
        for (int e = 0; e < 4; e++) d[e] = g_adj_s[j + e];
        uint4 v[4];
#pragma unroll
        for (int e = 0; e < 4; e++) v[e] = H[(size_t)d[e] * 8 + lane];
#pragma unroll
        for (int e = 0; e < 4; e++) acc_u4(a, v[e]);
    }
    for (; j < end; j++) {
        uint4 v = H[(size_t)g_adj_s[j] * 8 + lane];
        acc_u4(a, v);
    }
    float4* O = (float4*)out;                  // row = 16 float4
    O[(size_t)node * 16 + lane * 2] = make_float4(a[0], a[1], a[2], a[3]);
    O[(size_t)node * 16 + lane * 2 + 1] = make_float4(a[4], a[5], a[6], a[7]);
}

// ---------------- launch ----------------------------------------------------
extern "C" void kernel_launch(void* const* d_in, const int* in_sizes, int n_in,
                              void* d_out, int out_size) {
    const float* feat = (const float*)d_in[0];
    const int* ei = (const int*)d_in[1];
    const float* W_l = (const float*)d_in[2];
    const float* W_r = (const float*)d_in[3];
    const float* W_out = (const float*)d_in[4];
    const float* mask1 = (const float*)d_in[5];
    const float* mask2 = (const float*)d_in[6];
    float* out = (float*)d_out;

    void *p_cd = nullptr, *p_cs = nullptr;
    cudaGetSymbolAddress(&p_cd, g_cnt_d);
    cudaGetSymbolAddress(&p_cs, g_cnt_s);
    cudaMemsetAsync(p_cd, 0, N_NODES * sizeof(int));
    cudaMemsetAsync(p_cs, 0, N_NODES * sizeof(int));

    k_pre<<<FEAT4_BLOCKS + CNT_BLOCKS, 256>>>(feat, ei);
    k_scan1<<<2 * NCHUNK, 1024>>>();
    k_scan3<<<2 * NCHUNK, 1024>>>();
    k_fill_d<<<FILLS_BLOCKS, 256>>>(ei);
    k_mlp<<<MLP_BLOCKS + FILLS_BLOCKS, 256>>>(W_l, W_r, W_out, mask1, mask2, ei);
    k_out<<<(N_NODES * 8) / 256, 256>>>(out);
}